// round 16
// baseline (speedup 1.0000x reference)
#include <cuda_runtime.h>
#include <cuda_fp16.h>

#define NB 32
#define NL 100
#define NT (NB*NL)      // 3200 tokens
#define ND 200
#define INDIM 360
#define EMBD 300
#define POSD 30
#define NERD 30
#define NREL 40

#define BM 32           // tokens per block tile (GEMM)
#define BN 64           // outputs per block tile (GEMM)
#define KC 16           // k chunk
#define AGG_ROWS 2      // l rows per agg block (grid 1600 -> full occupancy)
#define MH 50           // m per half (agg: two warp-groups split the m range)

typedef unsigned long long ull;

__device__ float g_xb[NT*ND];
__device__ float g_z[NT*ND];
__device__ float g_invden[NT];

__device__ __forceinline__ void fma2(ull& acc, ull a, ull b) {
    asm("fma.rn.f32x2 %0, %1, %2, %0;" : "+l"(acc) : "l"(a), "l"(b));
}
__device__ __forceinline__ ull add2(ull a, ull b) {
    ull r;
    asm("add.rn.f32x2 %0, %1, %2;" : "=l"(r) : "l"(a), "l"(b));
    return r;
}
__device__ __forceinline__ ull splat2(float v) {
    ull r; unsigned u = __float_as_uint(v);
    asm("mov.b64 %0, {%1, %1};" : "=l"(r) : "r"(u));
    return r;
}
__device__ __forceinline__ void unpack2(ull a, float& lo, float& hi) {
    unsigned l, h;
    asm("mov.b64 {%0, %1}, %2;" : "=r"(l), "=r"(h) : "l"(a));
    lo = __uint_as_float(l); hi = __uint_as_float(h);
}
// convert packed half2 -> packed f32x2 (64-bit pair)
__device__ __forceinline__ ull h2_to_f2(unsigned h2) {
    ull r;
    asm("{\n\t"
        ".reg .b16 a, b;\n\t"
        ".reg .f32 lo, hi;\n\t"
        "mov.b32 {a, b}, %1;\n\t"
        "cvt.f32.f16 lo, a;\n\t"
        "cvt.f32.f16 hi, b;\n\t"
        "mov.b64 %0, {lo, hi};\n\t"
        "}" : "=l"(r) : "r"(h2));
    return r;
}
// PDL: wait for the producer grid before touching its outputs
__device__ __forceinline__ void pdl_wait() {
    asm volatile("griddepcontrol.wait;" ::: "memory");
}

// gather one element of the concatenated embedding row (0 beyond INDIM)
__device__ __forceinline__ float gatherA(int k, int wofs, int pofs, int nofs,
                                         const float* __restrict__ emb,
                                         const float* __restrict__ pos_emb,
                                         const float* __restrict__ ner_emb) {
    if (k < EMBD)        return emb[wofs + k];
    if (k < EMBD+POSD)   return pos_emb[pofs + (k - EMBD)];
    if (k < INDIM)       return ner_emb[nofs + (k - EMBD - POSD)];
    return 0.f;
}

// ---------------------------------------------------------------------------
// Fused front kernel (432 blocks):
//   blocks [0,32):   denom + mask for batch b = blockIdx.x
//   blocks [32,432): preprocessor GEMM with fused embedding gather
//     (triple-buffered smem, prefetch distance 2)
// ---------------------------------------------------------------------------
typedef float AsT[KC][BM+4];
typedef float BsT[KC][BN+4];

__global__ __launch_bounds__(256) void front_kernel(
        const int* __restrict__ adj,
        const int* __restrict__ words,
        const int* __restrict__ pos,
        const int* __restrict__ ner,
        const float* __restrict__ emb,
        const float* __restrict__ pos_emb,
        const float* __restrict__ ner_emb,
        const float* __restrict__ Wp,
        const float* __restrict__ bp,
        float* __restrict__ out_mask, int write_mask,
        float* __restrict__ C) {
    __shared__ __align__(16) char sbuf[NL*NL*4];   // 40 KB union
    int tid = threadIdx.x;

    if (blockIdx.x < NB) {
        int* A = (int*)sbuf;
        int b = blockIdx.x;
        const int* src = adj + b*NL*NL;
        for (int i = tid; i < NL*NL; i += 256) A[i] = src[i];
        __syncthreads();
        if (tid < NL) {
            int rc = 0, cc = 0;
            #pragma unroll 4
            for (int m = 0; m < NL; m++) {
                rc += (A[tid*NL + m] != 0);
                cc += (A[m*NL + tid] != 0);
            }
            g_invden[b*NL + tid] = 1.0f / (float)(rc + 1);
            if (write_mask)
                out_mask[b*NL + tid] = (rc + cc == 0) ? 1.0f : 0.0f;
        }
        return;
    }

    AsT* As = (AsT*)sbuf;
    BsT* Bs = (BsT*)(sbuf + 3*sizeof(AsT));
    const int K = INDIM;
    const int NC = (K + KC - 1) / KC;              // 23
    int idx = blockIdx.x - NB;
    int t0 = (idx >> 2) * BM;
    int j0 = (idx & 3) * BN;

    int tx = tid & 15, ty = tid >> 4;
    int lkk = tid & 15;
    int lrow = tid >> 4;

    int ta = t0 + lrow, tb = t0 + lrow + 16;
    int wa = words[ta]*EMBD, wb = words[tb]*EMBD;
    int pa = pos[ta]*POSD,  pb = pos[tb]*POSD;
    int na = ner[ta]*NERD,  nb = ner[tb]*NERD;

    float rA0[2], rB0[4], rA1[2], rB1[4];

#define LDG_CHUNK(RA, RB, CI)                                              \
    {                                                                      \
        int k = (CI)*KC + lkk;                                             \
        RA[0] = gatherA(k, wa, pa, na, emb, pos_emb, ner_emb);             \
        RA[1] = gatherA(k, wb, pb, nb, emb, pos_emb, ner_emb);             \
        _Pragma("unroll")                                                  \
        for (int it = 0; it < 4; it++) {                                   \
            int j = lrow + it*16;                                          \
            RB[it] = (k < K && (j0 + j) < ND) ? Wp[(j0 + j)*K + k] : 0.f;  \
        }                                                                  \
    }
#define STS_CHUNK(RA, RB, BI)                                              \
    {                                                                      \
        As[BI][lkk][lrow]      = RA[0];                                    \
        As[BI][lkk][lrow + 16] = RA[1];                                    \
        _Pragma("unroll")                                                  \
        for (int it = 0; it < 4; it++) Bs[BI][lkk][lrow + it*16] = RB[it]; \
    }
#define COMPUTE_CHUNK(BI)                                                  \
    {                                                                      \
        _Pragma("unroll")                                                  \
        for (int kk = 0; kk < KC; kk++) {                                  \
            float2 a = *(const float2*)&As[BI][kk][2*tx];                  \
            const ull* bpx = (const ull*)&Bs[BI][kk][4*ty];                \
            ull b01 = bpx[0], b23 = bpx[1];                                \
            ull a0 = splat2(a.x), a1 = splat2(a.y);                        \
            fma2(acc[0][0], a0, b01); fma2(acc[0][1], a0, b23);            \
            fma2(acc[1][0], a1, b01); fma2(acc[1][1], a1, b23);            \
        }                                                                  \
    }

    LDG_CHUNK(rA0, rB0, 0)
    STS_CHUNK(rA0, rB0, 0)
    LDG_CHUNK(rA1, rB1, 1)
    __syncthreads();

    ull acc[2][2];
    #pragma unroll
    for (int i = 0; i < 2; i++) { acc[i][0] = 0ull; acc[i][1] = 0ull; }

    for (int c = 0; c < NC; c += 2) {
        int b0 = c % 3, b1 = (c+1) % 3, b2 = (c+2) % 3;
        if (c + 2 < NC) LDG_CHUNK(rA0, rB0, c+2)
        COMPUTE_CHUNK(b0)
        if (c + 1 < NC) STS_CHUNK(rA1, rB1, b1)
        __syncthreads();
        if (c + 1 < NC) {
            if (c + 3 < NC) LDG_CHUNK(rA1, rB1, c+3)
            COMPUTE_CHUNK(b1)
            if (c + 2 < NC) STS_CHUNK(rA0, rB0, b2)
            __syncthreads();
        }
    }
#undef LDG_CHUNK
#undef STS_CHUNK
#undef COMPUTE_CHUNK

    int tbase = t0 + 2*tx;
    int jbase = j0 + 4*ty;
    #pragma unroll
    for (int i = 0; i < 2; i++) {
        int tok = tbase + i;
        float a0, a1, a2, a3;
        unpack2(acc[i][0], a0, a1);
        unpack2(acc[i][1], a2, a3);
        if (jbase + 3 < ND) {
            float4 v;
            v.x = a0 + bp[jbase];
            v.y = a1 + bp[jbase+1];
            v.z = a2 + bp[jbase+2];
            v.w = a3 + bp[jbase+3];
            *(float4*)&C[tok*ND + jbase] = v;
        } else {
            float av[4] = {a0, a1, a2, a3};
            #pragma unroll
            for (int j = 0; j < 4; j++)
                if (jbase + j < ND)
                    C[tok*ND + jbase + j] = av[j] + bp[jbase + j];
        }
    }
}

// ---------------------------------------------------------------------------
// Layer GEMM (KC=16 double-buffered, f32x2 accumulators). PDL: W chunk-0
// staged before griddepcontrol.wait; z touched only after.
// ---------------------------------------------------------------------------
__global__ __launch_bounds__(256) void gemm_relu_kernel(const float* __restrict__ A,
                                                        const float* __restrict__ B,
                                                        const float* __restrict__ bias,
                                                        float* __restrict__ C) {
    const int K = ND;
    const int NC = (K + KC - 1) / KC;       // 13
    __shared__ __align__(16) float As[2][KC][BM+4];
    __shared__ __align__(16) float Bs[2][KC][BN+4];
    int tid = threadIdx.x;
    int tx = tid & 15, ty = tid >> 4;
    int t0 = blockIdx.x * BM;
    int j0 = blockIdx.y * BN;

    int lkk = tid & 15;
    int lrow = tid >> 4;

    float rA[2], rB[4];

    // producer-independent: stage W chunk 0 first
    #pragma unroll
    for (int it = 0; it < 4; it++) {
        int j = lrow + it*16;
        rB[it] = ((j0 + j) < ND) ? B[(j0 + j)*K + lkk] : 0.f;
    }
    #pragma unroll
    for (int it = 0; it < 4; it++) Bs[0][lkk][lrow + it*16] = rB[it];

    pdl_wait();   // producer (z writer) must be complete before A loads

    #pragma unroll
    for (int it = 0; it < 2; it++)
        rA[it] = A[(t0 + lrow + it*16)*K + lkk];
    #pragma unroll
    for (int it = 0; it < 2; it++) As[0][lkk][lrow + it*16] = rA[it];
    __syncthreads();

    ull acc[2][2];
    #pragma unroll
    for (int i = 0; i < 2; i++) { acc[i][0] = 0ull; acc[i][1] = 0ull; }

    for (int c = 0; c < NC; c++) {
        int cur = c & 1;
        if (c + 1 < NC) {
            int k = (c + 1) * KC + lkk;
            #pragma unroll
            for (int it = 0; it < 2; it++)
                rA[it] = (k < K) ? A[(t0 + lrow + it*16)*K + k] : 0.f;
            #pragma unroll
            for (int it = 0; it < 4; it++) {
                int j = lrow + it*16;
                rB[it] = (k < K && (j0 + j) < ND) ? B[(j0 + j)*K + k] : 0.f;
            }
        }
        #pragma unroll
        for (int kk = 0; kk < KC; kk++) {
            float2 a = *(const float2*)&As[cur][kk][2*tx];
            const ull* bpx = (const ull*)&Bs[cur][kk][4*ty];
            ull b01 = bpx[0], b23 = bpx[1];
            ull a0 = splat2(a.x), a1 = splat2(a.y);
            fma2(acc[0][0], a0, b01); fma2(acc[0][1], a0, b23);
            fma2(acc[1][0], a1, b01); fma2(acc[1][1], a1, b23);
        }
        if (c + 1 < NC) {
            int nxt = cur ^ 1;
            #pragma unroll
            for (int it = 0; it < 2; it++) As[nxt][lkk][lrow + it*16] = rA[it];
            #pragma unroll
            for (int it = 0; it < 4; it++) Bs[nxt][lkk][lrow + it*16] = rB[it];
        }
        __syncthreads();
    }

    int tbase = t0 + 2*tx;
    int jbase = j0 + 4*ty;
    #pragma unroll
    for (int i = 0; i < 2; i++) {
        int tok = tbase + i;
        float inv = g_invden[tok];
        float a0, a1, a2, a3;
        unpack2(acc[i][0], a0, a1);
        unpack2(acc[i][1], a2, a3);
        float4 v;
        v.x = fmaxf((a0 + 2.f*bias[jbase])   * inv, 0.f);
        v.y = fmaxf((a1 + 2.f*bias[jbase+1]) * inv, 0.f);
        v.z = fmaxf((a2 + 2.f*bias[jbase+2]) * inv, 0.f);
        v.w = fmaxf((a3 + 2.f*bias[jbase+3]) * inv, 0.f);
        if (jbase + 3 < ND)
            *(float4*)&C[tok*ND + jbase] = v;
        else {
            if (jbase   < ND) C[tok*ND + jbase]   = v.x;
            if (jbase+1 < ND) C[tok*ND + jbase+1] = v.y;
            if (jbase+2 < ND) C[tok*ND + jbase+2] = v.z;
            if (jbase+3 < ND) C[tok*ND + jbase+3] = v.w;
        }
    }
}

// ---------------------------------------------------------------------------
// Aggregation, FP16 Es, AGG_ROWS=2 (grid 1600 -> full occupancy):
//   Z[b,l,d] = x[b,l,d] + sum_m E[adj[b,l,m], d] * x[b,m,d]
// PDL: Es/adjs staging happens before griddepcontrol.wait; x touched after.
// ---------------------------------------------------------------------------
__global__ __launch_bounds__(256) void agg_kernel(const int* __restrict__ adj,
                                                  const float* __restrict__ dep,
                                                  const float* __restrict__ x,
                                                  float* __restrict__ z) {
    __shared__ __align__(16) __half2 EsH[NREL*ND/2];   // 16 KB
    __shared__ __align__(16) int adjs[NL*AGG_ROWS];    // 0.8 KB
    __shared__ __align__(16) float part[AGG_ROWS][ND]; // 1.6 KB
    int tid = threadIdx.x;
    int b = blockIdx.y;
    int l0 = blockIdx.x * AGG_ROWS;

    int dp = tid & 127;
    int mh = tid >> 7;
    bool active = dp < ND/2;

    // stage Es as half2 + adjs byte offsets (producer-independent)
    {
        const float4* d4 = (const float4*)dep;
        for (int i = tid; i < NREL*ND/4; i += 256) {
            float4 v = d4[i];
            EsH[2*i]     = __floats2half2_rn(v.x, v.y);
            EsH[2*i + 1] = __floats2half2_rn(v.z, v.w);
        }
        for (int i = tid; i < AGG_ROWS*NL; i += 256) {
            int j = i & 1, m = i >> 1;
            adjs[i] = adj[(b*NL + l0 + j)*NL + m] * (ND*2);
        }
    }

    pdl_wait();   // x producer must be complete

    // seed: mh0 owns row 0, mh1 owns row 1
    ull acc[AGG_ROWS];
    #pragma unroll
    for (int i = 0; i < AGG_ROWS; i++) acc[i] = 0ull;
    if (active)
        acc[mh] = *(const ull*)&x[(b*NL + l0 + mh)*ND + 2*dp];
    __syncthreads();

    if (active) {
        const char* ep = (const char*)EsH + 4*dp;
        const float* xb = x + b*NL*ND + 2*dp + mh*MH*ND;
        const int*  ap = adjs + mh*MH*AGG_ROWS;

        ull xv0[5], xv1[5];
        #pragma unroll
        for (int s = 0; s < 5; s++) {
            xv0[s] = *(const ull*)(xb + s*ND);
            xv1[s] = *(const ull*)(xb + (5 + s)*ND);
        }

        #pragma unroll 1
        for (int ch = 0; ch < 10; ch += 2) {
            {
                ull cv[5];
                #pragma unroll
                for (int s = 0; s < 5; s++) cv[s] = xv0[s];
                if (ch + 2 < 10) {
                    const float* px = xb + (ch + 2)*5*ND;
                    #pragma unroll
                    for (int s = 0; s < 5; s++)
                        xv0[s] = *(const ull*)(px + s*ND);
                }
                const int* apc = ap + ch*5*AGG_ROWS;
                #pragma unroll
                for (int s = 0; s < 5; s++) {
                    const int2 r01 = *(const int2*)&apc[s*AGG_ROWS];
                    fma2(acc[0], h2_to_f2(*(const unsigned*)(ep + r01.x)), cv[s]);
                    fma2(acc[1], h2_to_f2(*(const unsigned*)(ep + r01.y)), cv[s]);
                }
            }
            {
                ull cv[5];
                #pragma unroll
                for (int s = 0; s < 5; s++) cv[s] = xv1[s];
                if (ch + 3 < 10) {
                    const float* px = xb + (ch + 3)*5*ND;
                    #pragma unroll
                    for (int s = 0; s < 5; s++)
                        xv1[s] = *(const ull*)(px + s*ND);
                }
                const int* apc = ap + (ch + 1)*5*AGG_ROWS;
                #pragma unroll
                for (int s = 0; s < 5; s++) {
                    const int2 r01 = *(const int2*)&apc[s*AGG_ROWS];
                    fma2(acc[0], h2_to_f2(*(const unsigned*)(ep + r01.x)), cv[s]);
                    fma2(acc[1], h2_to_f2(*(const unsigned*)(ep + r01.y)), cv[s]);
                }
            }
        }

        // export the row the OTHER half finalizes
        *(ull*)&part[1 - mh][2*dp] = acc[1 - mh];
    }
    __syncthreads();
    if (active) {
        ull p = *(const ull*)&part[mh][2*dp];
        *(ull*)&z[(b*NL + l0 + mh)*ND + 2*dp] = add2(acc[mh], p);
    }
}

// ---------------------------------------------------------------------------
static inline void launch_pdl(const void* fn, dim3 g, dim3 b, void** args) {
    cudaLaunchConfig_t cfg = {};
    cfg.gridDim = g; cfg.blockDim = b;
    cfg.dynamicSmemBytes = 0; cfg.stream = 0;
    cudaLaunchAttribute attr[1];
    attr[0].id = cudaLaunchAttributeProgrammaticStreamSerialization;
    attr[0].val.programmaticStreamSerializationAllowed = 1;
    cfg.attrs = attr; cfg.numAttrs = 1;
    if (cudaLaunchKernelExC(&cfg, fn, args) != cudaSuccess) {
        // fallback: plain launch without PDL
        cfg.attrs = nullptr; cfg.numAttrs = 0;
        cudaLaunchKernelExC(&cfg, fn, args);
    }
}

extern "C" void kernel_launch(void* const* d_in, const int* in_sizes, int n_in,
                              void* d_out, int out_size) {
    const int*   adj     = (const int*)  d_in[0];
    const int*   words   = (const int*)  d_in[1];
    const int*   pos     = (const int*)  d_in[2];
    const int*   ner     = (const int*)  d_in[3];
    const float* emb     = (const float*)d_in[4];
    const float* pos_emb = (const float*)d_in[5];
    const float* ner_emb = (const float*)d_in[6];
    const float* dep     = (const float*)d_in[7];
    const float* Wp      = (const float*)d_in[8];
    const float* bp      = (const float*)d_in[9];
    const float* W0      = (const float*)d_in[10];
    const float* b0      = (const float*)d_in[11];
    const float* W1      = (const float*)d_in[12];
    const float* b1      = (const float*)d_in[13];
    float* out = (float*)d_out;

    float *xb, *z;
    cudaGetSymbolAddress((void**)&xb, g_xb);
    cudaGetSymbolAddress((void**)&z,  g_z);

    int write_mask = (out_size >= NT*ND + NT) ? 1 : 0;
    float* mask_ptr = out + NT*ND;

    dim3 ggrid(NT/BM, (ND + BN - 1)/BN);        // (100, 4) = 400 blocks
    dim3 agrid(NL/AGG_ROWS, NB);                // (50, 32) = 1600 blocks

    front_kernel<<<NB + 400, 256>>>(adj, words, pos, ner, emb, pos_emb, ner_emb,
                                    Wp, bp, mask_ptr, write_mask, xb);

    {   void* a[] = {(void*)&adj, (void*)&dep, (void*)&xb, (void*)&z};
        launch_pdl((const void*)agg_kernel, agrid, dim3(256), a); }
    {   void* a[] = {(void*)&z, (void*)&W0, (void*)&b0, (void*)&xb};
        launch_pdl((const void*)gemm_relu_kernel, ggrid, dim3(256), a); }
    {   void* a[] = {(void*)&adj, (void*)&dep, (void*)&xb, (void*)&z};
        launch_pdl((const void*)agg_kernel, agrid, dim3(256), a); }
    {   void* a[] = {(void*)&z, (void*)&W1, (void*)&b1, (void*)&out};
        launch_pdl((const void*)gemm_relu_kernel, ggrid, dim3(256), a); }
}

// round 17
// speedup vs baseline: 1.0610x; 1.0610x over previous
#include <cuda_runtime.h>
#include <cuda_fp16.h>

#define NB 32
#define NL 100
#define NT (NB*NL)      // 3200 tokens
#define ND 200
#define INDIM 360
#define EMBD 300
#define POSD 30
#define NERD 30
#define NREL 40

#define BM 32           // tokens per block tile (GEMM)
#define BN 64           // outputs per block tile (GEMM)
#define KC 16           // k chunk
#define AGG_ROWS 4      // l rows per agg block (R15 best config)
#define MH 50           // m per half (agg: two warp-groups split the m range)

typedef unsigned long long ull;

__device__ float g_xb[NT*ND];
__device__ float g_z[NT*ND];
__device__ float g_invden[NT];

__device__ __forceinline__ void fma2(ull& acc, ull a, ull b) {
    asm("fma.rn.f32x2 %0, %1, %2, %0;" : "+l"(acc) : "l"(a), "l"(b));
}
__device__ __forceinline__ ull add2(ull a, ull b) {
    ull r;
    asm("add.rn.f32x2 %0, %1, %2;" : "=l"(r) : "l"(a), "l"(b));
    return r;
}
__device__ __forceinline__ ull splat2(float v) {
    ull r; unsigned u = __float_as_uint(v);
    asm("mov.b64 %0, {%1, %1};" : "=l"(r) : "r"(u));
    return r;
}
__device__ __forceinline__ void unpack2(ull a, float& lo, float& hi) {
    unsigned l, h;
    asm("mov.b64 {%0, %1}, %2;" : "=r"(l), "=r"(h) : "l"(a));
    lo = __uint_as_float(l); hi = __uint_as_float(h);
}
// convert packed half2 -> packed f32x2 (64-bit pair)
__device__ __forceinline__ ull h2_to_f2(unsigned h2) {
    ull r;
    asm("{\n\t"
        ".reg .b16 a, b;\n\t"
        ".reg .f32 lo, hi;\n\t"
        "mov.b32 {a, b}, %1;\n\t"
        "cvt.f32.f16 lo, a;\n\t"
        "cvt.f32.f16 hi, b;\n\t"
        "mov.b64 %0, {lo, hi};\n\t"
        "}" : "=l"(r) : "r"(h2));
    return r;
}
// PDL: wait for the producer grid before touching its outputs
__device__ __forceinline__ void pdl_wait() {
    asm volatile("griddepcontrol.wait;" ::: "memory");
}

// gather one element of the concatenated embedding row (0 beyond INDIM)
__device__ __forceinline__ float gatherA(int k, int wofs, int pofs, int nofs,
                                         const float* __restrict__ emb,
                                         const float* __restrict__ pos_emb,
                                         const float* __restrict__ ner_emb) {
    if (k < EMBD)        return emb[wofs + k];
    if (k < EMBD+POSD)   return pos_emb[pofs + (k - EMBD)];
    if (k < INDIM)       return ner_emb[nofs + (k - EMBD - POSD)];
    return 0.f;
}

// ---------------------------------------------------------------------------
// Fused front kernel (432 blocks):
//   blocks [0,32):   denom + mask for batch b = blockIdx.x
//   blocks [32,432): preprocessor GEMM with fused embedding gather
//     (triple-buffered smem, prefetch distance 2)
// ---------------------------------------------------------------------------
typedef float AsT[KC][BM+4];
typedef float BsT[KC][BN+4];

__global__ __launch_bounds__(256) void front_kernel(
        const int* __restrict__ adj,
        const int* __restrict__ words,
        const int* __restrict__ pos,
        const int* __restrict__ ner,
        const float* __restrict__ emb,
        const float* __restrict__ pos_emb,
        const float* __restrict__ ner_emb,
        const float* __restrict__ Wp,
        const float* __restrict__ bp,
        float* __restrict__ out_mask, int write_mask,
        float* __restrict__ C) {
    __shared__ __align__(16) char sbuf[NL*NL*4];   // 40 KB union
    int tid = threadIdx.x;

    if (blockIdx.x < NB) {
        int* A = (int*)sbuf;
        int b = blockIdx.x;
        const int* src = adj + b*NL*NL;
        for (int i = tid; i < NL*NL; i += 256) A[i] = src[i];
        __syncthreads();
        if (tid < NL) {
            int rc = 0, cc = 0;
            #pragma unroll 4
            for (int m = 0; m < NL; m++) {
                rc += (A[tid*NL + m] != 0);
                cc += (A[m*NL + tid] != 0);
            }
            g_invden[b*NL + tid] = 1.0f / (float)(rc + 1);
            if (write_mask)
                out_mask[b*NL + tid] = (rc + cc == 0) ? 1.0f : 0.0f;
        }
        return;
    }

    AsT* As = (AsT*)sbuf;
    BsT* Bs = (BsT*)(sbuf + 3*sizeof(AsT));
    const int K = INDIM;
    const int NC = (K + KC - 1) / KC;              // 23
    int idx = blockIdx.x - NB;
    int t0 = (idx >> 2) * BM;
    int j0 = (idx & 3) * BN;

    int tx = tid & 15, ty = tid >> 4;
    int lkk = tid & 15;
    int lrow = tid >> 4;

    int ta = t0 + lrow, tb = t0 + lrow + 16;
    int wa = words[ta]*EMBD, wb = words[tb]*EMBD;
    int pa = pos[ta]*POSD,  pb = pos[tb]*POSD;
    int na = ner[ta]*NERD,  nb = ner[tb]*NERD;

    float rA0[2], rB0[4], rA1[2], rB1[4];

#define LDG_CHUNK(RA, RB, CI)                                              \
    {                                                                      \
        int k = (CI)*KC + lkk;                                             \
        RA[0] = gatherA(k, wa, pa, na, emb, pos_emb, ner_emb);             \
        RA[1] = gatherA(k, wb, pb, nb, emb, pos_emb, ner_emb);             \
        _Pragma("unroll")                                                  \
        for (int it = 0; it < 4; it++) {                                   \
            int j = lrow + it*16;                                          \
            RB[it] = (k < K && (j0 + j) < ND) ? Wp[(j0 + j)*K + k] : 0.f;  \
        }                                                                  \
    }
#define STS_CHUNK(RA, RB, BI)                                              \
    {                                                                      \
        As[BI][lkk][lrow]      = RA[0];                                    \
        As[BI][lkk][lrow + 16] = RA[1];                                    \
        _Pragma("unroll")                                                  \
        for (int it = 0; it < 4; it++) Bs[BI][lkk][lrow + it*16] = RB[it]; \
    }
#define COMPUTE_CHUNK(BI)                                                  \
    {                                                                      \
        _Pragma("unroll")                                                  \
        for (int kk = 0; kk < KC; kk++) {                                  \
            float2 a = *(const float2*)&As[BI][kk][2*tx];                  \
            const ull* bpx = (const ull*)&Bs[BI][kk][4*ty];                \
            ull b01 = bpx[0], b23 = bpx[1];                                \
            ull a0 = splat2(a.x), a1 = splat2(a.y);                        \
            fma2(acc[0][0], a0, b01); fma2(acc[0][1], a0, b23);            \
            fma2(acc[1][0], a1, b01); fma2(acc[1][1], a1, b23);            \
        }                                                                  \
    }

    LDG_CHUNK(rA0, rB0, 0)
    STS_CHUNK(rA0, rB0, 0)
    LDG_CHUNK(rA1, rB1, 1)
    __syncthreads();

    ull acc[2][2];
    #pragma unroll
    for (int i = 0; i < 2; i++) { acc[i][0] = 0ull; acc[i][1] = 0ull; }

    for (int c = 0; c < NC; c += 2) {
        int b0 = c % 3, b1 = (c+1) % 3, b2 = (c+2) % 3;
        if (c + 2 < NC) LDG_CHUNK(rA0, rB0, c+2)
        COMPUTE_CHUNK(b0)
        if (c + 1 < NC) STS_CHUNK(rA1, rB1, b1)
        __syncthreads();
        if (c + 1 < NC) {
            if (c + 3 < NC) LDG_CHUNK(rA1, rB1, c+3)
            COMPUTE_CHUNK(b1)
            if (c + 2 < NC) STS_CHUNK(rA0, rB0, b2)
            __syncthreads();
        }
    }
#undef LDG_CHUNK
#undef STS_CHUNK
#undef COMPUTE_CHUNK

    int tbase = t0 + 2*tx;
    int jbase = j0 + 4*ty;
    #pragma unroll
    for (int i = 0; i < 2; i++) {
        int tok = tbase + i;
        float a0, a1, a2, a3;
        unpack2(acc[i][0], a0, a1);
        unpack2(acc[i][1], a2, a3);
        if (jbase + 3 < ND) {
            float4 v;
            v.x = a0 + bp[jbase];
            v.y = a1 + bp[jbase+1];
            v.z = a2 + bp[jbase+2];
            v.w = a3 + bp[jbase+3];
            *(float4*)&C[tok*ND + jbase] = v;
        } else {
            float av[4] = {a0, a1, a2, a3};
            #pragma unroll
            for (int j = 0; j < 4; j++)
                if (jbase + j < ND)
                    C[tok*ND + jbase + j] = av[j] + bp[jbase + j];
        }
    }
}

// ---------------------------------------------------------------------------
// Layer GEMM (KC=16 double-buffered, f32x2 accumulators). PDL: W chunk-0
// staged before griddepcontrol.wait; z touched only after.
// ---------------------------------------------------------------------------
__global__ __launch_bounds__(256) void gemm_relu_kernel(const float* __restrict__ A,
                                                        const float* __restrict__ B,
                                                        const float* __restrict__ bias,
                                                        float* __restrict__ C) {
    const int K = ND;
    const int NC = (K + KC - 1) / KC;       // 13
    __shared__ __align__(16) float As[2][KC][BM+4];
    __shared__ __align__(16) float Bs[2][KC][BN+4];
    int tid = threadIdx.x;
    int tx = tid & 15, ty = tid >> 4;
    int t0 = blockIdx.x * BM;
    int j0 = blockIdx.y * BN;

    int lkk = tid & 15;
    int lrow = tid >> 4;

    float rA[2], rB[4];

    // producer-independent: stage W chunk 0 first
    #pragma unroll
    for (int it = 0; it < 4; it++) {
        int j = lrow + it*16;
        rB[it] = ((j0 + j) < ND) ? B[(j0 + j)*K + lkk] : 0.f;
    }
    #pragma unroll
    for (int it = 0; it < 4; it++) Bs[0][lkk][lrow + it*16] = rB[it];

    pdl_wait();   // producer (z writer) must be complete before A loads

    #pragma unroll
    for (int it = 0; it < 2; it++)
        rA[it] = A[(t0 + lrow + it*16)*K + lkk];
    #pragma unroll
    for (int it = 0; it < 2; it++) As[0][lkk][lrow + it*16] = rA[it];
    __syncthreads();

    ull acc[2][2];
    #pragma unroll
    for (int i = 0; i < 2; i++) { acc[i][0] = 0ull; acc[i][1] = 0ull; }

    for (int c = 0; c < NC; c++) {
        int cur = c & 1;
        if (c + 1 < NC) {
            int k = (c + 1) * KC + lkk;
            #pragma unroll
            for (int it = 0; it < 2; it++)
                rA[it] = (k < K) ? A[(t0 + lrow + it*16)*K + k] : 0.f;
            #pragma unroll
            for (int it = 0; it < 4; it++) {
                int j = lrow + it*16;
                rB[it] = (k < K && (j0 + j) < ND) ? B[(j0 + j)*K + k] : 0.f;
            }
        }
        #pragma unroll
        for (int kk = 0; kk < KC; kk++) {
            float2 a = *(const float2*)&As[cur][kk][2*tx];
            const ull* bpx = (const ull*)&Bs[cur][kk][4*ty];
            ull b01 = bpx[0], b23 = bpx[1];
            ull a0 = splat2(a.x), a1 = splat2(a.y);
            fma2(acc[0][0], a0, b01); fma2(acc[0][1], a0, b23);
            fma2(acc[1][0], a1, b01); fma2(acc[1][1], a1, b23);
        }
        if (c + 1 < NC) {
            int nxt = cur ^ 1;
            #pragma unroll
            for (int it = 0; it < 2; it++) As[nxt][lkk][lrow + it*16] = rA[it];
            #pragma unroll
            for (int it = 0; it < 4; it++) Bs[nxt][lkk][lrow + it*16] = rB[it];
        }
        __syncthreads();
    }

    int tbase = t0 + 2*tx;
    int jbase = j0 + 4*ty;
    #pragma unroll
    for (int i = 0; i < 2; i++) {
        int tok = tbase + i;
        float inv = g_invden[tok];
        float a0, a1, a2, a3;
        unpack2(acc[i][0], a0, a1);
        unpack2(acc[i][1], a2, a3);
        float4 v;
        v.x = fmaxf((a0 + 2.f*bias[jbase])   * inv, 0.f);
        v.y = fmaxf((a1 + 2.f*bias[jbase+1]) * inv, 0.f);
        v.z = fmaxf((a2 + 2.f*bias[jbase+2]) * inv, 0.f);
        v.w = fmaxf((a3 + 2.f*bias[jbase+3]) * inv, 0.f);
        if (jbase + 3 < ND)
            *(float4*)&C[tok*ND + jbase] = v;
        else {
            if (jbase   < ND) C[tok*ND + jbase]   = v.x;
            if (jbase+1 < ND) C[tok*ND + jbase+1] = v.y;
            if (jbase+2 < ND) C[tok*ND + jbase+2] = v.z;
            if (jbase+3 < ND) C[tok*ND + jbase+3] = v.w;
        }
    }
}

// ---------------------------------------------------------------------------
// Aggregation, FP16 Es, AGG_ROWS=4 (R15 best config), split epilogue.
// PDL: Es/adjs staging (inputs only) before griddepcontrol.wait; x after.
//   Z[b,l,d] = x[b,l,d] + sum_m E[adj[b,l,m], d] * x[b,m,d]
// ---------------------------------------------------------------------------
__global__ __launch_bounds__(256) void agg_kernel(const int* __restrict__ adj,
                                                  const float* __restrict__ dep,
                                                  const float* __restrict__ x,
                                                  float* __restrict__ z) {
    __shared__ __align__(16) __half2 EsH[NREL*ND/2];   // 16 KB
    __shared__ __align__(16) int adjs[NL*4];           // 1.6 KB
    __shared__ __align__(16) float part[AGG_ROWS][ND]; // 3.2 KB
    int tid = threadIdx.x;
    int b = blockIdx.y;
    int l0 = blockIdx.x * AGG_ROWS;

    int dp = tid & 127;
    int mh = tid >> 7;
    bool active = dp < ND/2;

    // stage Es as half2 + adjs byte offsets (inputs only — before pdl_wait)
    {
        const float4* d4 = (const float4*)dep;
        for (int i = tid; i < NREL*ND/4; i += 256) {
            float4 v = d4[i];
            EsH[2*i]     = __floats2half2_rn(v.x, v.y);
            EsH[2*i + 1] = __floats2half2_rn(v.z, v.w);
        }
        for (int i = tid; i < AGG_ROWS*NL; i += 256) {
            int j = i & 3, m = i >> 2;
            adjs[i] = adj[(b*NL + l0 + j)*NL + m] * (ND*2);
        }
    }

    pdl_wait();   // x producer must be complete

    // seed: mh0 owns rows 0-1 (x-seeded), mh1 owns rows 2-3 (x-seeded)
    ull acc[AGG_ROWS];
    #pragma unroll
    for (int i = 0; i < AGG_ROWS; i++) acc[i] = 0ull;
    if (active) {
        if (mh == 0) {
            acc[0] = *(const ull*)&x[(b*NL + l0 + 0)*ND + 2*dp];
            acc[1] = *(const ull*)&x[(b*NL + l0 + 1)*ND + 2*dp];
        } else {
            acc[2] = *(const ull*)&x[(b*NL + l0 + 2)*ND + 2*dp];
            acc[3] = *(const ull*)&x[(b*NL + l0 + 3)*ND + 2*dp];
        }
    }
    __syncthreads();

    if (active) {
        const char* ep = (const char*)EsH + 4*dp;
        const float* xb = x + b*NL*ND + 2*dp + mh*MH*ND;
        const int*  ap = adjs + mh*MH*4;

        ull xv0[5], xv1[5];
        #pragma unroll
        for (int s = 0; s < 5; s++) {
            xv0[s] = *(const ull*)(xb + s*ND);
            xv1[s] = *(const ull*)(xb + (5 + s)*ND);
        }

        #pragma unroll 1
        for (int ch = 0; ch < 10; ch += 2) {
            {
                ull cv[5];
                #pragma unroll
                for (int s = 0; s < 5; s++) cv[s] = xv0[s];
                if (ch + 2 < 10) {
                    const float* px = xb + (ch + 2)*5*ND;
                    #pragma unroll
                    for (int s = 0; s < 5; s++)
                        xv0[s] = *(const ull*)(px + s*ND);
                }
                const int* apc = ap + ch*5*4;
                #pragma unroll
                for (int s = 0; s < 5; s++) {
                    const int4 r03 = *(const int4*)&apc[s*4];
                    fma2(acc[0], h2_to_f2(*(const unsigned*)(ep + r03.x)), cv[s]);
                    fma2(acc[1], h2_to_f2(*(const unsigned*)(ep + r03.y)), cv[s]);
                    fma2(acc[2], h2_to_f2(*(const unsigned*)(ep + r03.z)), cv[s]);
                    fma2(acc[3], h2_to_f2(*(const unsigned*)(ep + r03.w)), cv[s]);
                }
            }
            {
                ull cv[5];
                #pragma unroll
                for (int s = 0; s < 5; s++) cv[s] = xv1[s];
                if (ch + 3 < 10) {
                    const float* px = xb + (ch + 3)*5*ND;
                    #pragma unroll
                    for (int s = 0; s < 5; s++)
                        xv1[s] = *(const ull*)(px + s*ND);
                }
                const int* apc = ap + (ch + 1)*5*4;
                #pragma unroll
                for (int s = 0; s < 5; s++) {
                    const int4 r03 = *(const int4*)&apc[s*4];
                    fma2(acc[0], h2_to_f2(*(const unsigned*)(ep + r03.x)), cv[s]);
                    fma2(acc[1], h2_to_f2(*(const unsigned*)(ep + r03.y)), cv[s]);
                    fma2(acc[2], h2_to_f2(*(const unsigned*)(ep + r03.z)), cv[s]);
                    fma2(acc[3], h2_to_f2(*(const unsigned*)(ep + r03.w)), cv[s]);
                }
            }
        }

        // cross-half partials: each half exports the rows the OTHER finalizes
        if (mh == 0) {
            *(ull*)&part[2][2*dp] = acc[2];
            *(ull*)&part[3][2*dp] = acc[3];
        } else {
            *(ull*)&part[0][2*dp] = acc[0];
            *(ull*)&part[1][2*dp] = acc[1];
        }
    }
    __syncthreads();
    if (active) {
        if (mh == 0) {
            ull p0 = *(const ull*)&part[0][2*dp];
            ull p1 = *(const ull*)&part[1][2*dp];
            *(ull*)&z[(b*NL + l0 + 0)*ND + 2*dp] = add2(acc[0], p0);
            *(ull*)&z[(b*NL + l0 + 1)*ND + 2*dp] = add2(acc[1], p1);
        } else {
            ull p2 = *(const ull*)&part[2][2*dp];
            ull p3 = *(const ull*)&part[3][2*dp];
            *(ull*)&z[(b*NL + l0 + 2)*ND + 2*dp] = add2(acc[2], p2);
            *(ull*)&z[(b*NL + l0 + 3)*ND + 2*dp] = add2(acc[3], p3);
        }
    }
}

// ---------------------------------------------------------------------------
static inline void launch_pdl(const void* fn, dim3 g, dim3 b, void** args) {
    cudaLaunchConfig_t cfg = {};
    cfg.gridDim = g; cfg.blockDim = b;
    cfg.dynamicSmemBytes = 0; cfg.stream = 0;
    cudaLaunchAttribute attr[1];
    attr[0].id = cudaLaunchAttributeProgrammaticStreamSerialization;
    attr[0].val.programmaticStreamSerializationAllowed = 1;
    cfg.attrs = attr; cfg.numAttrs = 1;
    if (cudaLaunchKernelExC(&cfg, fn, args) != cudaSuccess) {
        // fallback: plain launch without PDL
        cfg.attrs = nullptr; cfg.numAttrs = 0;
        cudaLaunchKernelExC(&cfg, fn, args);
    }
}

extern "C" void kernel_launch(void* const* d_in, const int* in_sizes, int n_in,
                              void* d_out, int out_size) {
    const int*   adj     = (const int*)  d_in[0];
    const int*   words   = (const int*)  d_in[1];
    const int*   pos     = (const int*)  d_in[2];
    const int*   ner     = (const int*)  d_in[3];
    const float* emb     = (const float*)d_in[4];
    const float* pos_emb = (const float*)d_in[5];
    const float* ner_emb = (const float*)d_in[6];
    const float* dep     = (const float*)d_in[7];
    const float* Wp      = (const float*)d_in[8];
    const float* bp      = (const float*)d_in[9];
    const float* W0      = (const float*)d_in[10];
    const float* b0      = (const float*)d_in[11];
    const float* W1      = (const float*)d_in[12];
    const float* b1      = (const float*)d_in[13];
    float* out = (float*)d_out;

    float *xb, *z;
    cudaGetSymbolAddress((void**)&xb, g_xb);
    cudaGetSymbolAddress((void**)&z,  g_z);

    int write_mask = (out_size >= NT*ND + NT) ? 1 : 0;
    float* mask_ptr = out + NT*ND;

    dim3 ggrid(NT/BM, (ND + BN - 1)/BN);        // (100, 4) = 400 blocks
    dim3 agrid(NL/AGG_ROWS, NB);                // (25, 32) = 800 blocks

    front_kernel<<<NB + 400, 256>>>(adj, words, pos, ner, emb, pos_emb, ner_emb,
                                    Wp, bp, mask_ptr, write_mask, xb);

    {   void* a[] = {(void*)&adj, (void*)&dep, (void*)&xb, (void*)&z};
        launch_pdl((const void*)agg_kernel, agrid, dim3(256), a); }
    {   void* a[] = {(void*)&z, (void*)&W0, (void*)&b0, (void*)&xb};
        launch_pdl((const void*)gemm_relu_kernel, ggrid, dim3(256), a); }
    {   void* a[] = {(void*)&adj, (void*)&dep, (void*)&xb, (void*)&z};
        launch_pdl((const void*)agg_kernel, agrid, dim3(256), a); }
    {   void* a[] = {(void*)&z, (void*)&W1, (void*)&b1, (void*)&out};
        launch_pdl((const void*)gemm_relu_kernel, ggrid, dim3(256), a); }
}